// round 4
// baseline (speedup 1.0000x reference)
#include <cuda_runtime.h>
#include <cuda_bf16.h>

// out[b,h,i,j] = mask[b,h,i,j] - |slope(h) * (i - j)|
// B=2, NH=16, L=2048. HBM-bound: 512 MiB read + 512 MiB write.
//
// R4: 256-thread blocks, __launch_bounds__(256,5) to hold 40 warps/SM
// resident, 8 independent float4 chunks per thread (front-batched LDGs).
// Flat float4 indexing: row = idx4 >> 9, i = row & 2047, h = (row >> 11) & 15.

#define CHUNKS 8

__global__ __launch_bounds__(256, 5) void alibi_kernel(
    const float4* __restrict__ m4,
    float4* __restrict__ o4)
{
    // Per-thread base float4 index; chunks strided by total thread count
    // so every chunk's warp access stays 128B-coalesced.
    const unsigned g = blockIdx.x * 256u + threadIdx.x;
    const unsigned stride = gridDim.x * 256u;

    // Front-batch all 8 independent loads.
    unsigned idx[CHUNKS];
    float4 m[CHUNKS];
    #pragma unroll
    for (int c = 0; c < CHUNKS; c++) {
        idx[c] = g + c * stride;
        m[c] = __ldcs(&m4[idx[c]]);
    }

    #pragma unroll
    for (int c = 0; c < CHUNKS; c++) {
        const unsigned i4  = idx[c];
        const unsigned j0  = (i4 & 511u) << 2;      // column of first float
        const unsigned row = i4 >> 9;               // global row (b,h,i)
        const unsigned i   = row & 2047u;           // query position
        const unsigned h   = (row >> 11) & 15u;     // head

        // slope = 2^(-0.5*(h+1))  (NH=16 is a power of two)
        const float slope = exp2f(-0.5f * (float)(h + 1));
        const float fi = (float)i;

        float4 o;
        o.x = m[c].x - slope * fabsf(fi - (float)(j0 + 0));
        o.y = m[c].y - slope * fabsf(fi - (float)(j0 + 1));
        o.z = m[c].z - slope * fabsf(fi - (float)(j0 + 2));
        o.w = m[c].w - slope * fabsf(fi - (float)(j0 + 3));
        __stcs(&o4[i4], o);
    }
}

extern "C" void kernel_launch(void* const* d_in, const int* in_sizes, int n_in,
                              void* d_out, int out_size)
{
    const float4* mask = (const float4*)d_in[0];
    float4* out = (float4*)d_out;

    // total float4 elements = B*NH*L*L / 4 = 33554432
    const long long total4 = (long long)in_sizes[0] / 4;
    const int threads_total = (int)(total4 / CHUNKS);     // 4194304
    const int blocks = threads_total / 256;               // 16384

    alibi_kernel<<<blocks, 256>>>(mask, out);
}